// round 16
// baseline (speedup 1.0000x reference)
#include <cuda_runtime.h>
#include <cuda_fp16.h>

// Problem constants
#define Hh   256
#define Gg   1024
#define Tt   50
#define Kk   3
#define FSn  6
#define Bb   4096
#define BT   32            // batch rows per CTA
#define NTH  512
#define NWARP 16
#define NBLK (Bb/BT)       // 128 CTAs = 64 clusters = one wave

#define KC0  17            // layer0 K = 272 = h(256) | x(4) | pad
#define KC1  32            // layer1 K = 512 = h0 | h1
#define A0S  280
#define A1S  520
#define CS   260

#define W0SZ (KC0*64*32)   // uint4 units
#define W1SZ (KC1*64*32)
#define CHUNK_U4   2048    // one kc chunk = 32KB
#define CHUNK_BYTES 32768u
#define HALF_BYTES  16384u
#define HALF_U4     1024

__device__ uint4  g_w0e[W0SZ];
__device__ uint4  g_w1e[W1SZ];
__device__ uint4  g_w0d[3*W0SZ];
__device__ uint4  g_w1d[3*W1SZ];
__device__ float2 g_bias2[8*512];
__device__ __half g_eA1[NBLK*BT*A1S];   // encoder-final A1 snapshot
__device__ float  g_ec0[NBLK*BT*Hh];
__device__ float  g_ec1[NBLK*BT*Hh];

struct __align__(16) Smem {
  uint4  wbuf[2][CHUNK_U4];      // 64KB double-buffered weight staging
  unsigned long long mbar[4];    // full0, full1, empty0, empty1
  __half A0[BT*A0S];
  __half A1[BT*A1S];
  float  c0[BT*CS];
  float  c1[BT*CS];
  float  inp[BT*2];
  float  logit[BT*Kk];
};

// ---- fast activations ----
static __device__ __forceinline__ float tanh_fast(float v) {
  float r; asm("tanh.approx.f32 %0, %1;" : "=f"(r) : "f"(v)); return r;
}
static __device__ __forceinline__ float sigm(float v) {
  return fmaf(0.5f, tanh_fast(0.5f * v), 0.5f);
}

// ---- cluster / mbarrier helpers ----
static __device__ __forceinline__ unsigned ctarank() {
  unsigned r; asm("mov.u32 %0, %%cluster_ctarank;" : "=r"(r)); return r;
}
static __device__ __forceinline__ unsigned cvta_smem(const void* p) {
  return (unsigned)__cvta_generic_to_shared(p);
}
static __device__ __forceinline__ void cluster_sync() {
  asm volatile("barrier.cluster.arrive.aligned;" ::: "memory");
  asm volatile("barrier.cluster.wait.aligned;" ::: "memory");
}
static __device__ __forceinline__ void mbar_init(unsigned a, unsigned cnt) {
  asm volatile("mbarrier.init.shared.b64 [%0], %1;" :: "r"(a), "r"(cnt) : "memory");
}
static __device__ __forceinline__ void mbar_expect_tx(unsigned a, unsigned bytes) {
  asm volatile("mbarrier.arrive.expect_tx.shared.b64 _, [%0], %1;"
               :: "r"(a), "r"(bytes) : "memory");
}
static __device__ __forceinline__ void mbar_arrive(unsigned a) {
  asm volatile("mbarrier.arrive.shared.b64 _, [%0];" :: "r"(a) : "memory");
}
static __device__ __forceinline__ void mbar_arrive_peer(unsigned localAddr, unsigned peerRank) {
  asm volatile("{\n\t.reg .b32 ra;\n\t"
               "mapa.shared::cluster.u32 ra, %0, %1;\n\t"
               "mbarrier.arrive.shared::cluster.b64 _, [ra];\n\t}"
               :: "r"(localAddr), "r"(peerRank) : "memory");
}
static __device__ __forceinline__ void mbar_wait(unsigned a, unsigned ph) {
  asm volatile("{\n\t.reg .pred P;\n\t"
               "WL_%=:\n\t"
               "mbarrier.try_wait.parity.acquire.cta.shared::cta.b64 P, [%0], %1, 0x989680;\n\t"
               "@P bra WD_%=;\n\t"
               "bra WL_%=;\n\t"
               "WD_%=:\n\t}"
               :: "r"(a), "r"(ph) : "memory");
}
static __device__ __forceinline__ void mbar_wait_rel(unsigned a, unsigned ph) {
  asm volatile("{\n\t.reg .pred P;\n\t"
               "WL_%=:\n\t"
               "mbarrier.try_wait.parity.relaxed.cta.shared::cta.b64 P, [%0], %1, 0x989680;\n\t"
               "@P bra WD_%=;\n\t"
               "bra WL_%=;\n\t"
               "WD_%=:\n\t}"
               :: "r"(a), "r"(ph) : "memory");
}
// 1D bulk copy gmem->smem, multicast to both cluster CTAs, complete_tx on mbar.
static __device__ __forceinline__ void bulk_mc(unsigned dst, const void* src, unsigned mbar) {
  asm volatile(
    "cp.async.bulk.shared::cluster.global.mbarrier::complete_tx::bytes.multicast::cluster "
    "[%0], [%1], %2, [%3], %4;"
    :: "r"(dst), "l"(src), "r"(HALF_BYTES), "r"(mbar), "h"((unsigned short)0x3)
    : "memory");
}

// ===================== converter (unchanged layout) =====================
__global__ void conv_kernel(
    const float* __restrict__ eWih0, const float* __restrict__ eWhh0,
    const float* __restrict__ ebih0, const float* __restrict__ ebhh0,
    const float* __restrict__ eWih1, const float* __restrict__ eWhh1,
    const float* __restrict__ ebih1, const float* __restrict__ ebhh1,
    const float* __restrict__ dWih0, const float* __restrict__ dWhh0,
    const float* __restrict__ dbih0, const float* __restrict__ dbhh0,
    const float* __restrict__ dWih1, const float* __restrict__ dWhh1,
    const float* __restrict__ dbih1, const float* __restrict__ dbhh1)
{
  const int WU0 = W0SZ*4;
  const int WU1 = W1SZ*4;
  const int WTOT = WU0 + WU1 + 3*WU0 + 3*WU1;
  int idx = blockIdx.x * 256 + threadIdx.x;
  if (idx < WTOT) {
    unsigned* dst; int kind; int mode = 0; int local = idx;
    if (local < WU0) { dst = (unsigned*)g_w0e; kind = 0; }
    else if ((local -= WU0) < WU1) { dst = (unsigned*)g_w1e; kind = 1; }
    else if ((local -= WU1) < 3*WU0) {
      mode = local / WU0; local -= mode*WU0;
      dst = (unsigned*)g_w0d + (size_t)mode*WU0; kind = 2;
    } else {
      local -= 3*WU0; mode = local / WU1; local -= mode*WU1;
      dst = (unsigned*)g_w1d + (size_t)mode*WU1; kind = 3;
    }
    int q = local & 3, lane = (local>>2)&31, ntp = (local>>7)&63, kc = local>>13;
    int nt = 2*ntp + (q>>1);
    int ncol = nt*8 + (lane>>2);
    int j = (ncol&3)*256 + (ncol>>2);
    int k0 = kc*16 + (lane&3)*2 + (q&1)*8;
    float v0, v1;
    if (kind == 0) {
      v0 = (k0   < 256) ? eWhh0[j*256 + k0]   : ((k0   < 260) ? eWih0[j*4 + k0-256]   : 0.f);
      v1 = (k0+1 < 256) ? eWhh0[j*256 + k0+1] : ((k0+1 < 260) ? eWih0[j*4 + k0+1-256] : 0.f);
    } else if (kind == 1) {
      v0 = (k0   < 256) ? eWih1[j*256 + k0]   : eWhh1[j*256 + k0-256];
      v1 = (k0+1 < 256) ? eWih1[j*256 + k0+1] : eWhh1[j*256 + k0+1-256];
    } else if (kind == 2) {
      int base = mode*1024 + j;
      v0 = (k0   < 256) ? dWhh0[base*256 + k0]   : ((k0   < 258) ? dWih0[base*2 + k0-256]   : 0.f);
      v1 = (k0+1 < 256) ? dWhh0[base*256 + k0+1] : ((k0+1 < 258) ? dWih0[base*2 + k0+1-256] : 0.f);
    } else {
      int base = mode*1024 + j;
      v0 = (k0   < 256) ? dWih1[base*256 + k0]   : dWhh1[base*256 + k0-256];
      v1 = (k0+1 < 256) ? dWih1[base*256 + k0+1] : dWhh1[base*256 + k0+1-256];
    }
    __half2 h = __floats2half2_rn(v0, v1);
    dst[local] = *(unsigned*)&h;
  } else if (idx < WTOT + 8192) {
    int n = idx - WTOT;
    int seg = n >> 10, col = n & 1023;
    int j = (col&3)*256 + (col>>2);
    float v;
    if      (seg == 0) v = ebih0[j] + ebhh0[j];
    else if (seg == 1) v = ebih1[j] + ebhh1[j];
    else if (seg < 5)  { int m = seg-2; v = dbih0[m*1024+j] + dbhh0[m*1024+j]; }
    else               { int m = seg-5; v = dbih1[m*1024+j] + dbhh1[m*1024+j]; }
    ((float*)g_bias2)[seg*1024 + col] = v;
  }
}

// ===================== MMA primitives =====================
static __device__ __forceinline__ void ldsm4(unsigned* a, unsigned addr) {
  asm volatile("ldmatrix.sync.aligned.m8n8.x4.shared.b16 {%0,%1,%2,%3}, [%4];"
               : "=r"(a[0]),"=r"(a[1]),"=r"(a[2]),"=r"(a[3]) : "r"(addr));
}
static __device__ __forceinline__ void mma16816(float* c, const unsigned* a,
                                                unsigned b0, unsigned b1) {
  asm volatile("mma.sync.aligned.m16n8k16.row.col.f32.f16.f16.f32 "
               "{%0,%1,%2,%3},{%4,%5,%6,%7},{%8,%9},{%0,%1,%2,%3};"
               : "+f"(c[0]),"+f"(c[1]),"+f"(c[2]),"+f"(c[3])
               : "r"(a[0]),"r"(a[1]),"r"(a[2]),"r"(a[3]),"r"(b0),"r"(b1));
}

// Weight pipeline context (uniform across threads)
struct Pipe {
  unsigned full0, full1, empty0, empty1, wb0, wb1;  // smem addresses
  const uint4 *wg0, *wg1;                            // generic ptrs to wbuf stages
  unsigned cc;                                       // global chunk counter
  int rank, tid;
};

// Warp w owns n-cols [w*64, w*64+64); B fragments come from smem-staged chunks.
template<int KC>
static __device__ __forceinline__ void mma_block(
    const __half* A, int As, const float2* bias2, int w, int lane,
    float C[8][2][4], Pipe& P,
    const uint4* __restrict__ Wp, const uint4* __restrict__ WpNext)
{
  #pragma unroll
  for (int nt = 0; nt < 8; nt++) {
    int n0 = (w*8 + nt)*8 + (lane&3)*2;
    float2 bv = bias2[n0>>1];
    #pragma unroll
    for (int mh = 0; mh < 2; mh++) {
      C[nt][mh][0] = bv.x; C[nt][mh][1] = bv.y;
      C[nt][mh][2] = bv.x; C[nt][mh][3] = bv.y;
    }
  }
  int m = lane>>3, r = lane&7;
  unsigned abase = cvta_smem(A);
  unsigned aAddr0 = abase + (unsigned)((((m&1)*8 + r)*As + (m>>1)*8)*2);
  unsigned aAddr1 = aAddr0 + (unsigned)(16*As*2);
  #pragma unroll 1
  for (int kc = 0; kc < KC; kc++) {
    unsigned st = P.cc & 1u;
    unsigned fp = (P.cc >> 1) & 1u;
    mbar_wait(st ? P.full1 : P.full0, fp);
    const uint4* bp = (st ? P.wg1 : P.wg0) + (w*4)*32 + lane;
    uint4 b0 = bp[0], b1 = bp[32], b2 = bp[64], b3 = bp[96];
    unsigned a0[4], a1[4];
    ldsm4(a0, aAddr0); ldsm4(a1, aAddr1);
    aAddr0 += 32; aAddr1 += 32;
    mma16816(C[0][0], a0, b0.x, b0.y);  mma16816(C[0][1], a1, b0.x, b0.y);
    mma16816(C[1][0], a0, b0.z, b0.w);  mma16816(C[1][1], a1, b0.z, b0.w);
    mma16816(C[2][0], a0, b1.x, b1.y);  mma16816(C[2][1], a1, b1.x, b1.y);
    mma16816(C[3][0], a0, b1.z, b1.w);  mma16816(C[3][1], a1, b1.z, b1.w);
    mma16816(C[4][0], a0, b2.x, b2.y);  mma16816(C[4][1], a1, b2.x, b2.y);
    mma16816(C[5][0], a0, b2.z, b2.w);  mma16816(C[5][1], a1, b2.z, b2.w);
    mma16816(C[6][0], a0, b3.x, b3.y);  mma16816(C[6][1], a1, b3.x, b3.y);
    mma16816(C[7][0], a0, b3.z, b3.w);  mma16816(C[7][1], a1, b3.z, b3.w);
    __syncwarp();
    if (lane == 0) {
      unsigned ea = st ? P.empty1 : P.empty0;
      mbar_arrive(ea);
      mbar_arrive_peer(ea, (unsigned)(P.rank ^ 1));
    }
    if (P.tid == 0) {
      const uint4* gsrc;
      if (kc + 2 < KC)      gsrc = Wp + (size_t)(kc+2)*CHUNK_U4;
      else if (WpNext)      gsrc = WpNext + (size_t)(kc+2-KC)*CHUNK_U4;
      else                  gsrc = (const uint4*)0;
      if (gsrc) {
        unsigned ea = st ? P.empty1 : P.empty0;
        unsigned fa = st ? P.full1 : P.full0;
        unsigned wa = st ? P.wb1 : P.wb0;
        mbar_wait_rel(ea, fp);          // all 32 warp-arrives (both CTAs) for chunk cc
        mbar_expect_tx(fa, CHUNK_BYTES);
        bulk_mc(wa + (unsigned)P.rank*HALF_BYTES, gsrc + P.rank*HALF_U4, fa);
      }
    }
    P.cc++;
  }
}

// In-register cell update (R15-validated).
static __device__ __forceinline__ void cell_epi(
    float C[8][2][4], int w, int lane, float* __restrict__ cS,
    __half* __restrict__ d1, int d1s, int off1, __half* __restrict__ d2)
{
  const bool even = (lane & 1) == 0;
  const int rbase = (lane>>2) + (even ? 0 : 8);
  const int uoff = (lane&3) >> 1;
  #pragma unroll
  for (int nt = 0; nt < 8; nt++) {
    int u = (w*8 + nt)*2 + uoff;
    #pragma unroll
    for (int mh = 0; mh < 2; mh++) {
      float tA = even ? C[nt][mh][2] : C[nt][mh][0];
      float tB = even ? C[nt][mh][3] : C[nt][mh][1];
      float rA = __shfl_xor_sync(0xffffffffu, tA, 1);
      float rB = __shfl_xor_sync(0xffffffffu, tB, 1);
      float gi, gf, gg, go;
      if (even) { gi = C[nt][mh][0]; gf = C[nt][mh][1]; gg = rA; go = rB; }
      else      { gi = rA; gf = rB; gg = C[nt][mh][2]; go = C[nt][mh][3]; }
      int row = mh*16 + rbase;
      float i_ = sigm(gi), f_ = sigm(gf);
      float g_ = tanh_fast(gg), o_ = sigm(go);
      float cold = cS[row*CS + u];
      float cn = f_*cold + i_*g_;
      cS[row*CS + u] = cn;
      __half hv = __float2half(o_ * tanh_fast(cn));
      d1[row*d1s + off1 + u] = hv;
      if (d2) d2[row*A1S + u] = hv;
    }
  }
}

// ===================== main kernel =====================
__global__ void __launch_bounds__(NTH, 1) __cluster_dims__(2, 1, 1)
mml_kernel(const float* __restrict__ x,
           const float* __restrict__ headW, const float* __restrict__ headB,
           const float* __restrict__ confW, const float* __restrict__ confB,
           float* __restrict__ out)
{
  extern __shared__ char raw[];
  Smem* s = reinterpret_cast<Smem*>(raw);
  const int tid = threadIdx.x, w = tid >> 5, lane = tid & 31;
  const int bid = blockIdx.x;
  const int row0 = bid * BT;
  const int rank = (int)ctarank();

  // ---- pipeline context ----
  Pipe P;
  {
    unsigned mb = cvta_smem(s->mbar);
    P.full0 = mb; P.full1 = mb + 8; P.empty0 = mb + 16; P.empty1 = mb + 24;
    P.wb0 = cvta_smem(s->wbuf[0]); P.wb1 = cvta_smem(s->wbuf[1]);
    P.wg0 = s->wbuf[0]; P.wg1 = s->wbuf[1];
    P.cc = 0; P.rank = rank; P.tid = tid;
  }

  // ---- init: zero state, init mbarriers ----
  {
    unsigned* a0u = (unsigned*)s->A0;
    unsigned* a1u = (unsigned*)s->A1;
    for (int i = tid; i < BT*A0S/2; i += NTH) a0u[i] = 0u;
    for (int i = tid; i < BT*A1S/2; i += NTH) a1u[i] = 0u;
    for (int i = tid; i < BT*CS; i += NTH) { s->c0[i] = 0.f; s->c1[i] = 0.f; }
    if (tid == 0) {
      mbar_init(P.full0, 1);  mbar_init(P.full1, 1);
      mbar_init(P.empty0, 32); mbar_init(P.empty1, 32);
    }
  }
  __syncthreads();
  cluster_sync();   // mbarriers visible cluster-wide before any multicast

  // prologue: produce chunks 0 and 1 (encoder layer-0)
  if (tid == 0) {
    mbar_expect_tx(P.full0, CHUNK_BYTES);
    bulk_mc(P.wb0 + (unsigned)rank*HALF_BYTES, g_w0e + rank*HALF_U4, P.full0);
    mbar_expect_tx(P.full1, CHUNK_BYTES);
    bulk_mc(P.wb1 + (unsigned)rank*HALF_BYTES, g_w0e + CHUNK_U4 + rank*HALF_U4, P.full1);
  }

  // ================= ENCODER =================
  for (int t = 0; t < Tt; t++) {
    if (tid < 128) {
      int b = tid >> 2, d = tid & 3;
      s->A0[b*A0S + 256 + d] = __float2half(x[(row0 + b)*(Tt*4) + t*4 + d]);
    }
    __syncthreads();
    float C[8][2][4];
    mma_block<KC0>(s->A0, A0S, g_bias2 + 0*512, w, lane, C, P, g_w0e, g_w1e);
    __syncthreads();
    cell_epi(C, w, lane, s->c0, s->A0, A0S, 0, s->A1);
    __syncthreads();
    mma_block<KC1>(s->A1, A1S, g_bias2 + 1*512, w, lane, C, P, g_w1e,
                   (t < Tt-1) ? g_w0e : g_w0d);
    __syncthreads();
    cell_epi(C, w, lane, s->c1, s->A1, A1S, 256, (__half*)nullptr);
  }
  __syncthreads();

  // ---- snapshot encoder-final state to global scratch ----
  {
    unsigned* du = (unsigned*)(g_eA1 + (size_t)bid*(BT*A1S));
    const unsigned* a1u = (const unsigned*)s->A1;
    for (int i = tid; i < BT*A1S/2; i += NTH) du[i] = a1u[i];
    float* e0 = g_ec0 + (size_t)bid*(BT*Hh);
    float* e1 = g_ec1 + (size_t)bid*(BT*Hh);
    for (int i = tid; i < BT*Hh; i += NTH) {
      int row = i >> 8, u = i & 255;
      e0[i] = s->c0[row*CS + u];
      e1[i] = s->c1[row*CS + u];
    }
  }

  // ---- confidence head ----
  for (int task = w; task < BT*Kk; task += NWARP) {
    int b = task / Kk, k = task - b*Kk;
    float p = 0.f;
    for (int u = lane; u < Hh; u += 32)
      p += __half2float(s->A1[b*A1S + 256 + u]) * confW[k*Hh + u];
    #pragma unroll
    for (int off = 16; off; off >>= 1) p += __shfl_down_sync(0xffffffffu, p, off);
    if (lane == 0) s->logit[b*Kk + k] = p + confB[k];
  }
  __syncthreads();
  if (tid < BT) {
    int r = row0 + tid;
    float l0 = s->logit[tid*Kk], l1 = s->logit[tid*Kk+1], l2 = s->logit[tid*Kk+2];
    float m = fmaxf(l0, fmaxf(l1, l2));
    float e0 = __expf(l0-m), e1 = __expf(l1-m), e2 = __expf(l2-m);
    float inv = 1.f / (e0 + e1 + e2);
    float* cp = out + (size_t)Bb*Kk*FSn*2 + (size_t)r*Kk;
    cp[0] = e0*inv; cp[1] = e1*inv; cp[2] = e2*inv;
  }

  // ================= DECODER =================
  for (int km = 0; km < Kk; km++) {
    __syncthreads();
    {  // restore encoder-final state from global scratch
      unsigned* a1u = (unsigned*)s->A1;
      const unsigned* eu = (const unsigned*)(g_eA1 + (size_t)bid*(BT*A1S));
      for (int i = tid; i < BT*A1S/2; i += NTH) a1u[i] = eu[i];
      unsigned* a0u = (unsigned*)s->A0;
      for (int i = tid; i < BT*128; i += NTH) {
        int b = i >> 7, c = i & 127;
        a0u[b*(A0S/2) + c] = eu[b*(A1S/2) + c];
      }
      const float* e0 = g_ec0 + (size_t)bid*(BT*Hh);
      const float* e1 = g_ec1 + (size_t)bid*(BT*Hh);
      for (int i = tid; i < BT*Hh; i += NTH) {
        int row = i >> 8, u = i & 255;
        s->c0[row*CS + u] = e0[i];
        s->c1[row*CS + u] = e1[i];
      }
      if (tid < BT*2) {
        int b = tid >> 1, d = tid & 1;
        s->inp[tid] = x[(row0 + b)*(Tt*4) + (Tt-1)*4 + d];
      }
    }
    __syncthreads();

    const uint4* w0p = g_w0d + (size_t)km*W0SZ;
    const uint4* w1p = g_w1d + (size_t)km*W1SZ;
    const float2* b0p = g_bias2 + (2+km)*512;
    const float2* b1p = g_bias2 + (5+km)*512;

    for (int t = 0; t < FSn; t++) {
      if (tid < 64) {
        int b = tid >> 1, d = tid & 1;
        s->A0[b*A0S + 256 + d] = __float2half(s->inp[b*2 + d]);
      }
      __syncthreads();
      float C[8][2][4];
      mma_block<KC0>(s->A0, A0S, b0p, w, lane, C, P, w0p, w1p);
      __syncthreads();
      cell_epi(C, w, lane, s->c0, s->A0, A0S, 0, s->A1);
      __syncthreads();
      // next block after this one:
      const uint4* nxt;
      if (t < FSn-1)      nxt = w0p;
      else if (km < Kk-1) nxt = g_w0d + (size_t)(km+1)*W0SZ;
      else                nxt = (const uint4*)0;
      mma_block<KC1>(s->A1, A1S, b1p, w, lane, C, P, w1p, nxt);
      __syncthreads();
      cell_epi(C, w, lane, s->c1, s->A1, A1S, 256, (__half*)nullptr);
      __syncthreads();
      // head
      for (int task = w; task < BT*2; task += NWARP) {
        int b = task >> 1, d = task & 1;
        float p = 0.f;
        const float* hw = headW + (size_t)(km*2 + d)*Hh;
        for (int u = lane; u < Hh; u += 32)
          p += __half2float(s->A1[b*A1S + 256 + u]) * hw[u];
        #pragma unroll
        for (int off = 16; off; off >>= 1) p += __shfl_down_sync(0xffffffffu, p, off);
        if (lane == 0) {
          p += headB[km*2 + d];
          s->inp[b*2 + d] = p;
          int r = row0 + b;
          out[((((size_t)r*Kk + km)*FSn + t)*2) + d] = p;
        }
      }
      __syncthreads();
    }
  }
  cluster_sync();   // no CTA exits while peer pipeline traffic could target it
}

extern "C" void kernel_launch(void* const* d_in, const int* in_sizes, int n_in,
                              void* d_out, int out_size) {
  (void)in_sizes; (void)n_in; (void)out_size;
  const float* x     = (const float*)d_in[0];
  const float* eWih0 = (const float*)d_in[1];
  const float* eWhh0 = (const float*)d_in[2];
  const float* ebih0 = (const float*)d_in[3];
  const float* ebhh0 = (const float*)d_in[4];
  const float* eWih1 = (const float*)d_in[5];
  const float* eWhh1 = (const float*)d_in[6];
  const float* ebih1 = (const float*)d_in[7];
  const float* ebhh1 = (const float*)d_in[8];
  const float* dWih0 = (const float*)d_in[9];
  const float* dWhh0 = (const float*)d_in[10];
  const float* dbih0 = (const float*)d_in[11];
  const float* dbhh0 = (const float*)d_in[12];
  const float* dWih1 = (const float*)d_in[13];
  const float* dWhh1 = (const float*)d_in[14];
  const float* dbih1 = (const float*)d_in[15];
  const float* dbhh1 = (const float*)d_in[16];
  const float* headW = (const float*)d_in[17];
  const float* headB = (const float*)d_in[18];
  const float* confW = (const float*)d_in[19];
  const float* confB = (const float*)d_in[20];
  float* out = (float*)d_out;

  const int WU0 = W0SZ*4, WU1 = W1SZ*4;
  const int total = WU0 + WU1 + 3*WU0 + 3*WU1 + 8192;
  conv_kernel<<<(total + 255)/256, 256>>>(
      eWih0, eWhh0, ebih0, ebhh0, eWih1, eWhh1, ebih1, ebhh1,
      dWih0, dWhh0, dbih0, dbhh0, dWih1, dWhh1, dbih1, dbhh1);

  const int smem_bytes = (int)sizeof(Smem);
  cudaFuncSetAttribute(mml_kernel, cudaFuncAttributeMaxDynamicSharedMemorySize,
                       smem_bytes);
  mml_kernel<<<NBLK, NTH, smem_bytes>>>(x, headW, headB, confW, confB, out);
}

// round 17
// speedup vs baseline: 1.1541x; 1.1541x over previous
#include <cuda_runtime.h>
#include <cuda_fp16.h>

// Problem constants
#define Hh   256
#define Gg   1024
#define Tt   50
#define Kk   3
#define FSn  6
#define Bb   4096
#define BT   32            // batch rows per CTA (exact: 4096 = 32*128)
#define NTH  512
#define NWARP 16
#define NBLK (Bb/BT)       // 128 CTAs = one wave

#define KC0  17            // layer0 K = 272 = h(256) | x(4) | pad
#define KC1  32            // layer1 K = 512 = h0 | h1
#define A0S  280           // padded row stride (halves)
#define A1S  520
#define CS   260           // c-state row stride (floats)

#define W0SZ (KC0*64*32)   // uint4 units
#define W1SZ (KC1*64*32)

__device__ uint4  g_w0e[W0SZ];
__device__ uint4  g_w1e[W1SZ];
__device__ uint4  g_w0d[3*W0SZ];
__device__ uint4  g_w1d[3*W1SZ];
__device__ float2 g_bias2[8*512];
__device__ __half g_eA1[NBLK*BT*A1S];   // encoder-final [h0|h1] snapshot
__device__ float  g_ec0[NBLK*BT*Hh];
__device__ float  g_ec1[NBLK*BT*Hh];

struct Smem {
  __half A0[2][BT*A0S];   // double-buffered layer0 input [h0|x|pad]
  __half A1[2][BT*A1S];   // double-buffered layer1 input [h0|h1|pad]
  float  c0[BT*CS];
  float  c1[BT*CS];
  float  logit[BT*Kk];
};

// ---- fast activations ----
static __device__ __forceinline__ float tanh_fast(float v) {
  float r; asm("tanh.approx.f32 %0, %1;" : "=f"(r) : "f"(v)); return r;
}
static __device__ __forceinline__ float sigm(float v) {
  return fmaf(0.5f, tanh_fast(0.5f * v), 0.5f);
}

// zero-register L1 prefetch of a warp's first TWO B chunks
static __device__ __forceinline__ void pf_chunk(const uint4* __restrict__ Wp,
                                                int w, int lane) {
  const uint4* p = Wp + (size_t)(w*4)*32 + lane;
  asm volatile("prefetch.global.L1 [%0];" :: "l"(p));
  asm volatile("prefetch.global.L1 [%0];" :: "l"(p + 32));
  asm volatile("prefetch.global.L1 [%0];" :: "l"(p + 64));
  asm volatile("prefetch.global.L1 [%0];" :: "l"(p + 96));
  asm volatile("prefetch.global.L1 [%0];" :: "l"(p + 2048));
  asm volatile("prefetch.global.L1 [%0];" :: "l"(p + 2080));
  asm volatile("prefetch.global.L1 [%0];" :: "l"(p + 2112));
  asm volatile("prefetch.global.L1 [%0];" :: "l"(p + 2144));
}

// ===================== converter: fp32 weights -> f16 B-fragment layout =====================
__global__ void conv_kernel(
    const float* __restrict__ eWih0, const float* __restrict__ eWhh0,
    const float* __restrict__ ebih0, const float* __restrict__ ebhh0,
    const float* __restrict__ eWih1, const float* __restrict__ eWhh1,
    const float* __restrict__ ebih1, const float* __restrict__ ebhh1,
    const float* __restrict__ dWih0, const float* __restrict__ dWhh0,
    const float* __restrict__ dbih0, const float* __restrict__ dbhh0,
    const float* __restrict__ dWih1, const float* __restrict__ dWhh1,
    const float* __restrict__ dbih1, const float* __restrict__ dbhh1)
{
  const int WU0 = W0SZ*4;
  const int WU1 = W1SZ*4;
  const int WTOT = WU0 + WU1 + 3*WU0 + 3*WU1;
  int idx = blockIdx.x * 256 + threadIdx.x;
  if (idx < WTOT) {
    unsigned* dst; int kind; int mode = 0; int local = idx;
    if (local < WU0) { dst = (unsigned*)g_w0e; kind = 0; }
    else if ((local -= WU0) < WU1) { dst = (unsigned*)g_w1e; kind = 1; }
    else if ((local -= WU1) < 3*WU0) {
      mode = local / WU0; local -= mode*WU0;
      dst = (unsigned*)g_w0d + (size_t)mode*WU0; kind = 2;
    } else {
      local -= 3*WU0; mode = local / WU1; local -= mode*WU1;
      dst = (unsigned*)g_w1d + (size_t)mode*WU1; kind = 3;
    }
    int q = local & 3, lane = (local>>2)&31, ntp = (local>>7)&63, kc = local>>13;
    int nt = 2*ntp + (q>>1);
    int ncol = nt*8 + (lane>>2);
    int j = (ncol&3)*256 + (ncol>>2);
    int k0 = kc*16 + (lane&3)*2 + (q&1)*8;
    float v0, v1;
    if (kind == 0) {
      v0 = (k0   < 256) ? eWhh0[j*256 + k0]   : ((k0   < 260) ? eWih0[j*4 + k0-256]   : 0.f);
      v1 = (k0+1 < 256) ? eWhh0[j*256 + k0+1] : ((k0+1 < 260) ? eWih0[j*4 + k0+1-256] : 0.f);
    } else if (kind == 1) {
      v0 = (k0   < 256) ? eWih1[j*256 + k0]   : eWhh1[j*256 + k0-256];
      v1 = (k0+1 < 256) ? eWih1[j*256 + k0+1] : eWhh1[j*256 + k0+1-256];
    } else if (kind == 2) {
      int base = mode*1024 + j;
      v0 = (k0   < 256) ? dWhh0[base*256 + k0]   : ((k0   < 258) ? dWih0[base*2 + k0-256]   : 0.f);
      v1 = (k0+1 < 256) ? dWhh0[base*256 + k0+1] : ((k0+1 < 258) ? dWih0[base*2 + k0+1-256] : 0.f);
    } else {
      int base = mode*1024 + j;
      v0 = (k0   < 256) ? dWih1[base*256 + k0]   : dWhh1[base*256 + k0-256];
      v1 = (k0+1 < 256) ? dWih1[base*256 + k0+1] : dWhh1[base*256 + k0+1-256];
    }
    __half2 h = __floats2half2_rn(v0, v1);
    dst[local] = *(unsigned*)&h;
  } else if (idx < WTOT + 8192) {
    int n = idx - WTOT;
    int seg = n >> 10, col = n & 1023;
    int j = (col&3)*256 + (col>>2);
    float v;
    if      (seg == 0) v = ebih0[j] + ebhh0[j];
    else if (seg == 1) v = ebih1[j] + ebhh1[j];
    else if (seg < 5)  { int m = seg-2; v = dbih0[m*1024+j] + dbhh0[m*1024+j]; }
    else               { int m = seg-5; v = dbih1[m*1024+j] + dbhh1[m*1024+j]; }
    ((float*)g_bias2)[seg*1024 + col] = v;
  }
}

// ===================== MMA primitives =====================
static __device__ __forceinline__ void ldsm4(unsigned* a, unsigned addr) {
  asm volatile("ldmatrix.sync.aligned.m8n8.x4.shared.b16 {%0,%1,%2,%3}, [%4];"
               : "=r"(a[0]),"=r"(a[1]),"=r"(a[2]),"=r"(a[3]) : "r"(addr));
}
static __device__ __forceinline__ void mma16816(float* c, const unsigned* a,
                                                unsigned b0, unsigned b1) {
  asm volatile("mma.sync.aligned.m16n8k16.row.col.f32.f16.f16.f32 "
               "{%0,%1,%2,%3},{%4,%5,%6,%7},{%8,%9},{%0,%1,%2,%3};"
               : "+f"(c[0]),"+f"(c[1]),"+f"(c[2]),"+f"(c[3])
               : "r"(a[0]),"r"(a[1]),"r"(a[2]),"r"(a[3]),"r"(b0),"r"(b1));
}

// Warp w owns n-cols [w*64, w*64+64); R15-proven register weight streaming.
template<int KC>
static __device__ __forceinline__ void mma_block(
    const __half* A, int As, const uint4* __restrict__ Wp,
    const float2* __restrict__ bias2, int w, int lane, float C[8][2][4])
{
  #pragma unroll
  for (int nt = 0; nt < 8; nt++) {
    int n0 = (w*8 + nt)*8 + (lane&3)*2;
    float2 bv = bias2[n0>>1];
    #pragma unroll
    for (int mh = 0; mh < 2; mh++) {
      C[nt][mh][0] = bv.x; C[nt][mh][1] = bv.y;
      C[nt][mh][2] = bv.x; C[nt][mh][3] = bv.y;
    }
  }
  int m = lane>>3, r = lane&7;
  unsigned abase = (unsigned)__cvta_generic_to_shared(A);
  unsigned aAddr0 = abase + (unsigned)((((m&1)*8 + r)*As + (m>>1)*8)*2);
  unsigned aAddr1 = aAddr0 + (unsigned)(16*As*2);
  const uint4* p = Wp + (size_t)(w*4)*32 + lane;
  uint4 buf[4];
  #pragma unroll
  for (int i = 0; i < 4; i++) buf[i] = p[i*32];
  #pragma unroll 1
  for (int kc = 0; kc < KC; kc++) {
    unsigned a0[4], a1[4];
    ldsm4(a0, aAddr0); ldsm4(a1, aAddr1);
    aAddr0 += 32; aAddr1 += 32;
    const uint4* pn = p + (size_t)((kc+1 < KC) ? (kc+1) : 0) * 2048;
    #pragma unroll
    for (int ntp = 0; ntp < 4; ntp++) {
      uint4 bw = buf[ntp];
      buf[ntp] = pn[ntp*32];
      mma16816(C[2*ntp  ][0], a0, bw.x, bw.y);
      mma16816(C[2*ntp  ][1], a1, bw.x, bw.y);
      mma16816(C[2*ntp+1][0], a0, bw.z, bw.w);
      mma16816(C[2*ntp+1][1], a1, bw.z, bw.w);
    }
  }
}

// In-register cell update (R15-validated, 2-shfl gate exchange).
static __device__ __forceinline__ void cell_epi(
    float C[8][2][4], int w, int lane, float* __restrict__ cS,
    __half* __restrict__ d1, int d1s, int off1, __half* __restrict__ d2)
{
  const bool even = (lane & 1) == 0;
  const int rbase = (lane>>2) + (even ? 0 : 8);
  const int uoff = (lane&3) >> 1;
  #pragma unroll
  for (int nt = 0; nt < 8; nt++) {
    int u = (w*8 + nt)*2 + uoff;
    #pragma unroll
    for (int mh = 0; mh < 2; mh++) {
      float tA = even ? C[nt][mh][2] : C[nt][mh][0];
      float tB = even ? C[nt][mh][3] : C[nt][mh][1];
      float rA = __shfl_xor_sync(0xffffffffu, tA, 1);
      float rB = __shfl_xor_sync(0xffffffffu, tB, 1);
      float gi, gf, gg, go;
      if (even) { gi = C[nt][mh][0]; gf = C[nt][mh][1]; gg = rA; go = rB; }
      else      { gi = rA; gf = rB; gg = C[nt][mh][2]; go = C[nt][mh][3]; }
      int row = mh*16 + rbase;
      float i_ = sigm(gi), f_ = sigm(gf);
      float g_ = tanh_fast(gg), o_ = sigm(go);
      float cold = cS[row*CS + u];
      float cn = f_*cold + i_*g_;
      cS[row*CS + u] = cn;
      __half hv = __float2half(o_ * tanh_fast(cn));
      d1[row*d1s + off1 + u] = hv;
      if (d2) d2[row*A1S + u] = hv;
    }
  }
}

// ===================== main kernel =====================
__global__ void __launch_bounds__(NTH, 1)
mml_kernel(const float* __restrict__ x,
           const float* __restrict__ headW, const float* __restrict__ headB,
           const float* __restrict__ confW, const float* __restrict__ confB,
           float* __restrict__ out)
{
  extern __shared__ char raw[];
  Smem* s = reinterpret_cast<Smem*>(raw);
  const int tid = threadIdx.x, w = tid >> 5, lane = tid & 31;
  const int bid = blockIdx.x;
  const int row0 = bid * BT;

  // ---- init: zero both A buffers + c; stage x(0) into A0[0] ----
  {
    unsigned* a0u = (unsigned*)s->A0;
    unsigned* a1u = (unsigned*)s->A1;
    for (int i = tid; i < 2*BT*A0S/2; i += NTH) a0u[i] = 0u;
    for (int i = tid; i < 2*BT*A1S/2; i += NTH) a1u[i] = 0u;
    for (int i = tid; i < BT*CS; i += NTH) { s->c0[i] = 0.f; s->c1[i] = 0.f; }
    if (tid < 128) {
      int b = tid >> 2, d = tid & 3;
      s->A0[0][b*A0S + 256 + d] = __float2half(x[(row0 + b)*(Tt*4) + 0*4 + d]);
    }
  }
  pf_chunk(g_w0e, w, lane);
  __syncthreads();

  // ================= ENCODER (2 barriers/step, double-buffered A) =================
  int pb = 0;
  for (int t = 0; t < Tt; t++) {
    const __half* A0p = s->A0[pb];
    __half*       A0n = s->A0[pb ^ 1];
    __half*       A1p = s->A1[pb];
    __half*       A1n = s->A1[pb ^ 1];
    float C[8][2][4];
    mma_block<KC0>(A0p, A0S, g_w0e, g_bias2 + 0*512, w, lane, C);
    pf_chunk(g_w1e, w, lane);
    cell_epi(C, w, lane, s->c0, A0n, A0S, 0, A1p);   // h0 -> next A0, current A1
    __syncthreads();                                  // Ba: epi0 visible for mma1
    mma_block<KC1>(A1p, A1S, g_w1e, g_bias2 + 1*512, w, lane, C);
    pf_chunk((t < Tt-1) ? g_w0e : g_w0d, w, lane);
    cell_epi(C, w, lane, s->c1, A1n, A1S, 256, (__half*)nullptr);  // h1 -> next A1
    if (t + 1 < Tt && tid < 128) {                    // stage x(t+1) into next A0
      int b = tid >> 2, d = tid & 3;
      A0n[b*A0S + 256 + d] = __float2half(x[(row0 + b)*(Tt*4) + (t+1)*4 + d]);
    }
    __syncthreads();                                  // Bb: epi1 + xstage visible
    pb ^= 1;
  }
  // pb == 0 now: final h0 in A0[0], final h1 in A1[0] cols 256+.

  // ---- snapshot encoder-final state to global scratch ----
  {
    unsigned* du = (unsigned*)(g_eA1 + (size_t)bid*(BT*A1S));
    const unsigned* a0u = (const unsigned*)s->A0[0];
    const unsigned* a1u = (const unsigned*)s->A1[0];
    for (int i = tid; i < BT*A1S/2; i += NTH) {
      int row = i / (A1S/2), c2 = i - row*(A1S/2);
      du[i] = (c2 < 128) ? a0u[row*(A0S/2) + c2] : a1u[i];
    }
    float* e0 = g_ec0 + (size_t)bid*(BT*Hh);
    float* e1 = g_ec1 + (size_t)bid*(BT*Hh);
    for (int i = tid; i < BT*Hh; i += NTH) {
      int row = i >> 8, u = i & 255;
      e0[i] = s->c0[row*CS + u];
      e1[i] = s->c1[row*CS + u];
    }
  }

  // ---- confidence head (h1 = A1[0] cols 256+) ----
  for (int task = w; task < BT*Kk; task += NWARP) {
    int b = task / Kk, k = task - b*Kk;
    float p = 0.f;
    for (int u = lane; u < Hh; u += 32)
      p += __half2float(s->A1[0][b*A1S + 256 + u]) * confW[k*Hh + u];
    #pragma unroll
    for (int off = 16; off; off >>= 1) p += __shfl_down_sync(0xffffffffu, p, off);
    if (lane == 0) s->logit[b*Kk + k] = p + confB[k];
  }
  __syncthreads();
  if (tid < BT) {
    int r = row0 + tid;
    float l0 = s->logit[tid*Kk], l1 = s->logit[tid*Kk+1], l2 = s->logit[tid*Kk+2];
    float m = fmaxf(l0, fmaxf(l1, l2));
    float e0 = __expf(l0-m), e1 = __expf(l1-m), e2 = __expf(l2-m);
    float inv = 1.f / (e0 + e1 + e2);
    float* cp = out + (size_t)Bb*Kk*FSn*2 + (size_t)r*Kk;
    cp[0] = e0*inv; cp[1] = e1*inv; cp[2] = e2*inv;
  }

  // ================= DECODER (3 barriers/step) =================
  for (int km = 0; km < Kk; km++) {
    __syncthreads();
    if (km > 0) {   // restore encoder-final state (mode 0 already has it in place)
      unsigned* a1u = (unsigned*)s->A1[0];
      unsigned* a0u = (unsigned*)s->A0[0];
      const unsigned* eu = (const unsigned*)(g_eA1 + (size_t)bid*(BT*A1S));
      for (int i = tid; i < BT*A1S/2; i += NTH) a1u[i] = eu[i];
      for (int i = tid; i < BT*128; i += NTH) {
        int b = i >> 7, c = i & 127;
        a0u[b*(A0S/2) + c] = eu[b*(A1S/2) + c];
      }
      const float* e0 = g_ec0 + (size_t)bid*(BT*Hh);
      const float* e1 = g_ec1 + (size_t)bid*(BT*Hh);
      for (int i = tid; i < BT*Hh; i += NTH) {
        int row = i >> 8, u = i & 255;
        s->c0[row*CS + u] = e0[i];
        s->c1[row*CS + u] = e1[i];
      }
    }
    if (tid < 64) {   // stage decoder input = x[:, -1, :2] into A0[0]
      int b = tid >> 1, d = tid & 1;
      s->A0[0][b*A0S + 256 + d] = __float2half(x[(row0 + b)*(Tt*4) + (Tt-1)*4 + d]);
    }
    __syncthreads();

    const uint4* w0p = g_w0d + (size_t)km*W0SZ;
    const uint4* w1p = g_w1d + (size_t)km*W1SZ;
    const float2* b0p = g_bias2 + (2+km)*512;
    const float2* b1p = g_bias2 + (5+km)*512;

    pb = 0;
    for (int t = 0; t < FSn; t++) {
      const __half* A0p = s->A0[pb];
      __half*       A0n = s->A0[pb ^ 1];
      __half*       A1p = s->A1[pb];
      __half*       A1n = s->A1[pb ^ 1];
      float C[8][2][4];
      mma_block<KC0>(A0p, A0S, w0p, b0p, w, lane, C);
      pf_chunk(w1p, w, lane);
      cell_epi(C, w, lane, s->c0, A0n, A0S, 0, A1p);
      __syncthreads();                                // Ba
      mma_block<KC1>(A1p, A1S, w1p, b1p, w, lane, C);
      {
        const uint4* nxt;
        if (t < FSn-1)      nxt = w0p;
        else if (km < Kk-1) nxt = g_w0d + (size_t)(km+1)*W0SZ;
        else                nxt = (const uint4*)0;
        if (nxt) pf_chunk(nxt, w, lane);
      }
      cell_epi(C, w, lane, s->c1, A1n, A1S, 256, (__half*)nullptr);
      __syncthreads();                                // Bb: h1(t) in A1n visible
      // head: reads h1(t) from A1n; writes out + next-step input into A0n
      for (int task = w; task < BT*2; task += NWARP) {
        int b = task >> 1, d = task & 1;
        float p = 0.f;
        const float* hw = headW + (size_t)(km*2 + d)*Hh;
        for (int u = lane; u < Hh; u += 32)
          p += __half2float(A1n[b*A1S + 256 + u]) * hw[u];
        #pragma unroll
        for (int off = 16; off; off >>= 1) p += __shfl_down_sync(0xffffffffu, p, off);
        if (lane == 0) {
          p += headB[km*2 + d];
          A0n[b*A0S + 256 + d] = __float2half(p);
          int r = row0 + b;
          out[((((size_t)r*Kk + km)*FSn + t)*2) + d] = p;
        }
      }
      __syncthreads();                                // Bc: feedback staged
      pb ^= 1;
    }
  }
}

extern "C" void kernel_launch(void* const* d_in, const int* in_sizes, int n_in,
                              void* d_out, int out_size) {
  (void)in_sizes; (void)n_in; (void)out_size;
  const float* x     = (const float*)d_in[0];
  const float* eWih0 = (const float*)d_in[1];
  const float* eWhh0 = (const float*)d_in[2];
  const float* ebih0 = (const float*)d_in[3];
  const float* ebhh0 = (const float*)d_in[4];
  const float* eWih1 = (const float*)d_in[5];
  const float* eWhh1 = (const float*)d_in[6];
  const float* ebih1 = (const float*)d_in[7];
  const float* ebhh1 = (const float*)d_in[8];
  const float* dWih0 = (const float*)d_in[9];
  const float* dWhh0 = (const float*)d_in[10];
  const float* dbih0 = (const float*)d_in[11];
  const float* dbhh0 = (const float*)d_in[12];
  const float* dWih1 = (const float*)d_in[13];
  const float* dWhh1 = (const float*)d_in[14];
  const float* dbih1 = (const float*)d_in[15];
  const float* dbhh1 = (const float*)d_in[16];
  const float* headW = (const float*)d_in[17];
  const float* headB = (const float*)d_in[18];
  const float* confW = (const float*)d_in[19];
  const float* confB = (const float*)d_in[20];
  float* out = (float*)d_out;

  // 1) pack weights/biases into fragment layout (f16)
  const int WU0 = W0SZ*4, WU1 = W1SZ*4;
  const int total = WU0 + WU1 + 3*WU0 + 3*WU1 + 8192;
  conv_kernel<<<(total + 255)/256, 256>>>(
      eWih0, eWhh0, ebih0, ebhh0, eWih1, eWhh1, ebih1, ebhh1,
      dWih0, dWhh0, dbih0, dbhh0, dWih1, dWhh1, dbih1, dbhh1);

  // 2) persistent LSTM kernel
  const int smem_bytes = (int)sizeof(Smem);
  cudaFuncSetAttribute(mml_kernel, cudaFuncAttributeMaxDynamicSharedMemorySize,
                       smem_bytes);
  mml_kernel<<<NBLK, NTH, smem_bytes>>>(x, headW, headB, confW, confB, out);
}